// round 9
// baseline (speedup 1.0000x reference)
#include <cuda_runtime.h>

#define EPSF 1e-8f
#define LNK   16
#define DST   255        // float4 groups per row
#define TUN   1020
#define NCH   8
#define QUADS 28
#define ROWS  112        // 4 * QUADS
#define SLOTB 464        // 29 x 16B per slot (112 floats + 16B pad)
#define PLB   14848      // 32 slots * 464 B per plane
#define PLF4  928        // PLB/16
#define ZWORD 14848      // zero region start (word index) = 4*PLB/4
#define ZBYTE 59392      // zero region byte offset (fits u16)
#define SCHW  176        // padded schedule entries per chunk (pad-to-4 per bin)
#define THR   1024

// dynamic smem word offsets
#define W_SCHED 14976            // s_pl: 14848 + 128 zero words
#define W_OFF   (W_SCHED + 704)  // sched: 8*176 u16 = 704 words
#define W_CUR   (W_OFF + 136)    // s_off: 8*17 ints
#define W_NL    (W_CUR + 136)
#define W_INV   (W_NL + 2*112*17)
#define W_LOSS  (W_INV + 16)
#define W_FIN   (W_LOSS + 32)
#define W_LAST  (W_FIN + 32)
#define W_TOTAL (W_LAST + 1)

__device__ float    g_partials[512];
__device__ unsigned g_count;   // zero-init; last block resets (deterministic)

__device__ __forceinline__ void lds128(unsigned a, unsigned long long& x,
                                       unsigned long long& y) {
    asm volatile("ld.shared.v2.u64 {%0,%1}, [%2];" : "=l"(x), "=l"(y) : "r"(a));
}
__device__ __forceinline__ unsigned long long addx2(unsigned long long a,
                                                    unsigned long long b) {
    unsigned long long r;
    asm("add.rn.f32x2 %0, %1, %2;" : "=l"(r) : "l"(a), "l"(b));
    return r;
}

__global__ __launch_bounds__(THR, 1) void loss_kernel(
    const float* __restrict__ pred,   // [B,1020]
    const float* __restrict__ dem,    // [B,255]
    const float* __restrict__ clu,    // [B,16]
    const float* __restrict__ caps,   // [16]
    const int*   __restrict__ t2l,    // [1020]
    float* __restrict__ out,
    int B, int nb, float invB)
{
    extern __shared__ float sm[];
    float*          s_pl    = sm;
    unsigned short* s_sched = (unsigned short*)(sm + W_SCHED);
    int*            s_off   = (int*)(sm + W_OFF);    // [8][17]
    int*            s_cur   = (int*)(sm + W_CUR);
    float*          s_nl    = sm + W_NL;              // [2][112*17]
    float*          s_inv   = sm + W_INV;
    float*          s_loss  = sm + W_LOSS;
    float*          s_fin   = sm + W_FIN;
    int*            s_last  = (int*)(sm + W_LAST);

    const int tid  = threadIdx.x;
    const int warp = tid >> 5;          // 0..31
    const int lane = tid & 31;
    const int base = blockIdx.x * ROWS;
    const unsigned pl32 = (unsigned)__cvta_generic_to_shared(s_pl);
    const bool stager = (warp < QUADS);

    // row byte-offsets (u32: tensors < 4 GB) and validity masks
    unsigned offR[4], offD[4];
    float    msk[4];
    #pragma unroll
    for (int i = 0; i < 4; ++i) {
        const int row = base + warp + QUADS * i;
        const bool ok = stager && (row < B);
        const unsigned rc = ok ? (unsigned)row : 0u;
        offR[i] = rc * (TUN * 4u);
        offD[i] = rc * (DST * 4u);
        msk[i]  = ok ? 1.0f : 0.0f;
    }

    float4 q0, q1, q2, q3;
    float  d0, d1, d2, d3;

    #define LOADCH(cn)                                                           \
    if (stager) {                                                                \
        unsigned lx = (unsigned)(lane << 4);                                     \
        float gm = 1.0f;                                                         \
        if ((cn) == 7 && lane == 31) { lx = 0u; gm = 0.0f; }                     \
        const unsigned rb = (unsigned)(cn) * 512u;                               \
        const unsigned db = (unsigned)(cn) * 128u;                               \
        q0 = *(const float4*)((const char*)pred + offR[0] + rb + lx);            \
        q1 = *(const float4*)((const char*)pred + offR[1] + rb + lx);            \
        q2 = *(const float4*)((const char*)pred + offR[2] + rb + lx);            \
        q3 = *(const float4*)((const char*)pred + offR[3] + rb + lx);            \
        d0 = *(const float*)((const char*)dem + offD[0] + db + (lx >> 2)) * (msk[0] * gm); \
        d1 = *(const float*)((const char*)dem + offD[1] + db + (lx >> 2)) * (msk[1] * gm); \
        d2 = *(const float*)((const char*)dem + offD[2] + db + (lx >> 2)) * (msk[2] * gm); \
        d3 = *(const float*)((const char*)dem + offD[3] + db + (lx >> 2)) * (msk[3] * gm); \
    }

    #define STSCH()                                                              \
    if (stager) {                                                                \
        const int bi = lane * 29 + warp;                                         \
        ((float4*)s_pl)[0 * PLF4 + bi] = make_float4(q0.x*d0, q1.x*d1, q2.x*d2, q3.x*d3); \
        ((float4*)s_pl)[1 * PLF4 + bi] = make_float4(q0.y*d0, q1.y*d1, q2.y*d2, q3.y*d3); \
        ((float4*)s_pl)[2 * PLF4 + bi] = make_float4(q0.z*d0, q1.z*d1, q2.z*d2, q3.z*d3); \
        ((float4*)s_pl)[3 * PLF4 + bi] = make_float4(q0.w*d0, q1.w*d1, q2.w*d2, q3.w*d3); \
    }

    // ------------- LDG chunk 0 ----------------------------------------------
    LOADCH(0);

    // ------------- schedule build: warp c (<8) sorts chunk c ----------------
    if (warp < 8) {
        const int c = warp;
        int* cur = s_cur + c * 17;
        int* off = s_off + c * 17;
        if (lane < 17) cur[lane] = 0;
        int bins[4];
        #pragma unroll
        for (int q = 0; q < 4; ++q) {
            const int t = c * 128 + q * 32 + lane;
            bins[q] = (t < TUN) ? t2l[t] : 16;
        }
        __syncwarp();
        #pragma unroll
        for (int q = 0; q < 4; ++q) {
            const unsigned peers = __match_any_sync(0xffffffffu, bins[q]);
            const int rank = __popc(peers & ((1u << lane) - 1u));
            if (rank == 0) cur[bins[q]] += __popc(peers);
            __syncwarp();
        }
        if (lane < 17) {                           // pad-to-4 exclusive scan
            int o = 0;
            for (int i = 0; i < lane; ++i) o += (cur[i] + 3) & ~3;
            off[lane] = o;
        }
        __syncwarp();
        for (int i = lane; i < SCHW; i += 32)
            s_sched[c * SCHW + i] = (unsigned short)ZBYTE;   // dummy -> zeros
        if (lane < 17) cur[lane] = off[lane];
        __syncwarp();
        #pragma unroll
        for (int q = 0; q < 4; ++q) {
            const unsigned peers = __match_any_sync(0xffffffffu, bins[q]);
            const int rank = __popc(peers & ((1u << lane) - 1u));
            const int bse  = cur[bins[q]];
            __syncwarp();
            if (rank == 0) cur[bins[q]] = bse + __popc(peers);
            __syncwarp();
            if (bins[q] < 16) {
                const int tl = q * 32 + lane;                  // chunk-local id
                const unsigned o = (unsigned)(tl & 3) * PLB
                                 + (unsigned)(tl >> 2) * SLOTB;
                s_sched[c * SCHW + bse + rank] = (unsigned short)o;
            }
        }
    }
    if (tid < 128) s_pl[ZWORD + tid] = 0.0f;       // 512B zero region
    if (tid < LNK) s_inv[tid] = 1.0f / (caps[tid] + EPSF);

    STSCH();                                        // stage chunk 0
    __syncthreads();

    // ------------- main loop ------------------------------------------------
    unsigned long long acc0 = 0ull, acc1 = 0ull;
    const int gb = warp & 15;                       // bin
    const int gh = warp >> 4;                       // half

    #pragma unroll 1
    for (int c = 0; c < NCH; ++c) {
        if (c < NCH - 1) LOADCH(c + 1);

        // gather chunk c: 1 LDS.128 serves 4 rows
        {
            const unsigned lbase = pl32 + (unsigned)(lane << 4);
            const unsigned short* sc = s_sched + c * SCHW;
            const int lo = s_off[c * 17 + gb];
            const int half = (s_off[c * 17 + gb + 1] - lo) >> 1;   // even
            int k = lo + (gh ? half : 0);
            const int ke = k + half;
            for (; k < ke; k += 2) {
                unsigned long long x0, y0, x1, y1;
                lds128(lbase + sc[k],     x0, y0);
                lds128(lbase + sc[k + 1], x1, y1);
                acc0 = addx2(acc0, x0);  acc1 = addx2(acc1, y0);
                acc0 = addx2(acc0, x1);  acc1 = addx2(acc1, y1);
            }
        }
        __syncthreads();
        if (c < NCH - 1) {
            STSCH();
            __syncthreads();
        }
    }

    // ------------- stats -----------------------------------------------------
    {
        const float r0v = __uint_as_float((unsigned)(acc0 & 0xffffffffull));
        const float r1v = __uint_as_float((unsigned)(acc0 >> 32));
        const float r2v = __uint_as_float((unsigned)(acc1 & 0xffffffffull));
        const float r3v = __uint_as_float((unsigned)(acc1 >> 32));
        float* nl = s_nl + gh * (112 * 17);
        if (lane < QUADS) {
            nl[(lane          ) * 17 + gb] = r0v;
            nl[(lane + QUADS  ) * 17 + gb] = r1v;
            nl[(lane + 2*QUADS) * 17 + gb] = r2v;
            nl[(lane + 3*QUADS) * 17 + gb] = r3v;
        }
    }
    __syncthreads();

    float lsum = 0.0f;
    #pragma unroll
    for (int p = 0; p < 2; ++p) {
        const int rid = p * 64 + (warp << 1) + (lane >> 4);
        const int j = lane & 15;
        const int brow = base + rid;
        const bool rok = (rid < ROWS) && (brow < B);
        const float traf = rok ? (s_nl[rid * 17 + j] + s_nl[112 * 17 + rid * 17 + j]) : 0.0f;
        const float u   = traf * s_inv[j];
        const float cur = rok ? clu[(size_t)brow * LNK + j] : 0.0f;

        float smn = u;
        #pragma unroll
        for (int off = 1; off < 16; off <<= 1)
            smn += __shfl_xor_sync(0xffffffffu, smn, off);
        const float mean = smn * (1.0f / 16.0f);

        const float dv = u - mean;
        float q2v = dv * dv;
        float dot = u * cur;
        float mx  = u;
        #pragma unroll
        for (int off = 1; off < 16; off <<= 1) {
            q2v += __shfl_xor_sync(0xffffffffu, q2v, off);
            dot += __shfl_xor_sync(0xffffffffu, dot, off);
            mx   = fmaxf(mx, __shfl_xor_sync(0xffffffffu, mx, off));
        }
        if (j == 0 && rok)
            lsum += 0.3f * (q2v * (1.0f / 15.0f)) + 0.5f * dot + 0.2f * mx;
    }
    lsum += __shfl_xor_sync(0xffffffffu, lsum, 16);
    if (lane == 0) s_loss[warp] = lsum;
    __syncthreads();

    // ------------- block partial + deterministic last-block reduce ----------
    if (warp == 0) {
        float t = s_loss[lane];
        #pragma unroll
        for (int off = 16; off; off >>= 1)
            t += __shfl_xor_sync(0xffffffffu, t, off);
        if (lane == 0) {
            g_partials[blockIdx.x] = t;
            __threadfence();
            const unsigned old = atomicAdd(&g_count, 1u);
            *s_last = (old == (unsigned)(nb - 1));
        }
    }
    __syncthreads();

    if (*s_last) {
        float v = (tid < nb) ? __ldcg(&g_partials[tid]) : 0.0f;
        #pragma unroll
        for (int off = 16; off; off >>= 1)
            v += __shfl_xor_sync(0xffffffffu, v, off);
        if (lane == 0) s_fin[warp] = v;
        __syncthreads();
        if (warp == 0) {
            float t = s_fin[lane];
            #pragma unroll
            for (int off = 16; off; off >>= 1)
                t += __shfl_xor_sync(0xffffffffu, t, off);
            if (lane == 0) {
                out[0] = t * invB;
                g_count = 0;
            }
        }
    }
}

extern "C" void kernel_launch(void* const* d_in, const int* in_sizes, int n_in,
                              void* d_out, int out_size)
{
    const float* pred = (const float*)d_in[0];
    const float* dem  = (const float*)d_in[1];
    const float* clu  = (const float*)d_in[2];
    const float* caps = (const float*)d_in[3];
    const int*   t2l  = (const int*)d_in[4];
    float* out = (float*)d_out;

    const int B  = in_sizes[0] / TUN;           // 16384
    int nb = (B + ROWS - 1) / ROWS;             // 147
    if (nb > 512) nb = 512;

    const int smem_bytes = W_TOTAL * 4;         // ~79.4 KB
    cudaFuncSetAttribute(loss_kernel,
                         cudaFuncAttributeMaxDynamicSharedMemorySize, smem_bytes);
    loss_kernel<<<nb, THR, smem_bytes>>>(pred, dem, clu, caps, t2l, out,
                                         B, nb, 1.0f / (float)B);
}

// round 10
// speedup vs baseline: 1.4863x; 1.4863x over previous
#include <cuda_runtime.h>

#define EPSF 1e-8f
#define LNK   16
#define DST   255
#define TUN   1020
#define NCH   8
#define PAIRS 28          // row pairs per block
#define ROWS  56
#define SSTR  58          // words per group slot (28 pairs*2 + 2 pad)
#define PLW   (32*SSTR)   // 1856 words per plane
#define BUFDW (4*PLW)     // 7424 data words per buffer
#define BUFW  (BUFDW+64)  // + 64-word zero region per buffer
#define BUFB  (BUFW*4)    // 29952 bytes per buffer
#define ZBYTE (BUFDW*4)   // 29696: zero region byte offset (same in both buffers)
#define SCHW  144
#define THR   512

// dynamic smem layout (words)
#define W_SCHED (2*BUFW)                  // 14976
#define W_OFF   (W_SCHED + (NCH*SCHW)/2)  // + 576
#define W_CUR   (W_OFF + NCH*17)
#define W_NL    (W_CUR + NCH*17)
#define W_INV   (W_NL + ROWS*17)
#define W_LOSS  (W_INV + 16)
#define W_FIN   (W_LOSS + 16)
#define W_LAST  (W_FIN + THR)
#define W_TOTAL (W_LAST + 1)

__device__ float    g_partials[512];
__device__ unsigned g_count;   // zero-init; last block resets (deterministic)

__device__ __forceinline__ unsigned long long lds64(unsigned a) {
    unsigned long long v;
    asm volatile("ld.shared.b64 %0, [%1];" : "=l"(v) : "r"(a));
    return v;
}
__device__ __forceinline__ unsigned long long addx2(unsigned long long a,
                                                    unsigned long long b) {
    unsigned long long r;
    asm("add.rn.f32x2 %0, %1, %2;" : "=l"(r) : "l"(a), "l"(b));
    return r;
}

__global__ __launch_bounds__(THR, 2) void loss_kernel(
    const float* __restrict__ pred,   // [B,1020]
    const float* __restrict__ dem,    // [B,255]
    const float* __restrict__ clu,    // [B,16]
    const float* __restrict__ caps,   // [16]
    const int*   __restrict__ t2l,    // [1020]
    float* __restrict__ out,
    int B, int nb, float invB)
{
    extern __shared__ float sm[];
    float*          s_pl    = sm;                          // 2 buffers
    unsigned short* s_sched = (unsigned short*)(sm + W_SCHED);
    int*            s_off   = (int*)(sm + W_OFF);          // [8][17]
    int*            s_cur   = (int*)(sm + W_CUR);
    float*          s_nl    = sm + W_NL;                   // [56][17]
    float*          s_inv   = sm + W_INV;
    float*          s_loss  = sm + W_LOSS;
    float*          s_fin   = sm + W_FIN;
    int*            s_last  = (int*)(sm + W_LAST);

    const int tid  = threadIdx.x;
    const int warp = tid >> 5;          // 0..15; stages pairs warp, warp+16; gathers bin=warp
    const int lane = tid & 31;
    const int base = blockIdx.x * ROWS;
    const unsigned pl32 = (unsigned)__cvta_generic_to_shared(s_pl);

    float4 ra[2], rb[2];
    float  da[2], db[2];

    #define LOADCH(ch)                                                            \
    {                                                                             \
        const int gg = (ch) * 32 + lane;                                          \
        _Pragma("unroll")                                                         \
        for (int u = 0; u < 2; ++u) {                                             \
            const int pr = warp + 16 * u;                                         \
            const int r0 = base + pr, r1 = r0 + PAIRS;                            \
            const bool ok = (pr < PAIRS) && (gg < DST);                           \
            const bool o0 = ok && (r0 < B), o1 = ok && (r1 < B);                  \
            ra[u] = o0 ? ((const float4*)pred)[(size_t)r0 * DST + gg]             \
                       : make_float4(0,0,0,0);                                    \
            rb[u] = o1 ? ((const float4*)pred)[(size_t)r1 * DST + gg]             \
                       : make_float4(0,0,0,0);                                    \
            da[u] = o0 ? dem[(size_t)r0 * DST + gg] : 0.0f;                       \
            db[u] = o1 ? dem[(size_t)r1 * DST + gg] : 0.0f;                       \
        }                                                                         \
    }

    #define STSCH(buf)                                                            \
    {                                                                             \
        float* bp = s_pl + (buf) * BUFW;                                          \
        _Pragma("unroll")                                                         \
        for (int u = 0; u < 2; ++u) {                                             \
            const int pr = warp + 16 * u;                                         \
            if (pr < PAIRS) {                                                     \
                const int wb = lane * SSTR + pr * 2;                              \
                ((float2*)bp)[(0 * PLW + wb) >> 1] = make_float2(ra[u].x * da[u], rb[u].x * db[u]); \
                ((float2*)bp)[(1 * PLW + wb) >> 1] = make_float2(ra[u].y * da[u], rb[u].y * db[u]); \
                ((float2*)bp)[(2 * PLW + wb) >> 1] = make_float2(ra[u].z * da[u], rb[u].z * db[u]); \
                ((float2*)bp)[(3 * PLW + wb) >> 1] = make_float2(ra[u].w * da[u], rb[u].w * db[u]); \
            }                                                                     \
        }                                                                         \
    }

    // ------------- LDG chunk 0 ----------------------------------------------
    LOADCH(0);

    // ------------- schedule build: warp c (<8) sorts chunk c ----------------
    if (warp < 8) {
        const int c = warp;
        int* cur = s_cur + c * 17;
        int* off = s_off + c * 17;
        if (lane < 17) cur[lane] = 0;
        int bins[4];
        #pragma unroll
        for (int q = 0; q < 4; ++q) {
            const int t = c * 128 + q * 32 + lane;
            bins[q] = (t < TUN) ? t2l[t] : 16;
        }
        __syncwarp();
        #pragma unroll
        for (int q = 0; q < 4; ++q) {
            const unsigned peers = __match_any_sync(0xffffffffu, bins[q]);
            const int rank = __popc(peers & ((1u << lane) - 1u));
            if (rank == 0) cur[bins[q]] += __popc(peers);
            __syncwarp();
        }
        if (lane < 17) {                           // padded (even) exclusive scan
            int o = 0;
            for (int i = 0; i < lane; ++i) o += (cur[i] + 1) & ~1;
            off[lane] = o;
        }
        __syncwarp();
        for (int i = lane; i < SCHW; i += 32)
            s_sched[c * SCHW + i] = (unsigned short)ZBYTE;   // dummy -> zeros
        if (lane < 17) cur[lane] = off[lane];
        __syncwarp();
        #pragma unroll
        for (int q = 0; q < 4; ++q) {
            const unsigned peers = __match_any_sync(0xffffffffu, bins[q]);
            const int rank = __popc(peers & ((1u << lane) - 1u));
            const int bse  = cur[bins[q]];
            __syncwarp();
            if (rank == 0) cur[bins[q]] = bse + __popc(peers);
            __syncwarp();
            if (bins[q] < 16) {
                const int tl = q * 32 + lane;                  // chunk-local id
                const unsigned o = (unsigned)(tl & 3) * (PLW * 4)
                                 + (unsigned)(tl >> 2) * (SSTR * 4);
                s_sched[c * SCHW + bse + rank] = (unsigned short)o;
            }
        }
    }
    // zero regions of BOTH buffers (64 words each)
    if (tid >= 256 && tid < 384) {
        const int i = tid - 256;                   // 0..127
        s_pl[(i >> 6) * BUFW + BUFDW + (i & 63)] = 0.0f;
    }
    if (tid < LNK) s_inv[tid] = 1.0f / (caps[tid] + EPSF);

    STSCH(0);                                      // stage chunk 0 -> buffer 0
    __syncthreads();

    // ------------- main loop: LDG(c+1) | gather(c) | STS(c+1) | sync -------
    unsigned long long acc0 = 0ull, acc1 = 0ull;

    #pragma unroll 1
    for (int c = 0; c < NCH; ++c) {
        if (c < NCH - 1) LOADCH(c + 1);

        // gather chunk c from buffer (c&1); warp owns bin = warp
        {
            const unsigned lbase = pl32 + (unsigned)((c & 1) * BUFB)
                                 + (unsigned)(lane << 3);
            const unsigned short* sc = s_sched + c * SCHW;
            int k = s_off[c * 17 + warp];
            const int hi = s_off[c * 17 + warp + 1];
            #pragma unroll 2
            for (; k < hi; k += 2) {
                const unsigned o0 = sc[k];
                const unsigned o1 = sc[k + 1];
                acc0 = addx2(acc0, lds64(lbase + o0));
                acc1 = addx2(acc1, lds64(lbase + o1));
            }
        }

        // stage chunk c+1 into the OTHER buffer (safe: gather(c-1) synced)
        if (c < NCH - 1) STSCH((c + 1) & 1);
        __syncthreads();
    }

    // ------------- stats -----------------------------------------------------
    {
        const unsigned long long t = addx2(acc0, acc1);
        const float lo = __uint_as_float((unsigned)(t & 0xffffffffull));
        const float hi = __uint_as_float((unsigned)(t >> 32));
        if (lane < PAIRS) {
            s_nl[lane * 17 + warp] = lo;               // row = lane
            s_nl[(lane + PAIRS) * 17 + warp] = hi;     // row = lane + 28
        }
    }
    __syncthreads();

    float lsum = 0.0f;
    #pragma unroll
    for (int p = 0; p < 2; ++p) {
        const int rid = p * 32 + (warp << 1) + (lane >> 4);
        const int j = lane & 15;
        const int brow = base + rid;
        const bool rok = (rid < ROWS) && (brow < B);
        const float u   = rok ? s_nl[rid * 17 + j] * s_inv[j] : 0.0f;
        const float cur = rok ? clu[(size_t)brow * LNK + j] : 0.0f;

        float smn = u;
        #pragma unroll
        for (int off = 1; off < 16; off <<= 1)
            smn += __shfl_xor_sync(0xffffffffu, smn, off);
        const float mean = smn * (1.0f / 16.0f);

        const float dv = u - mean;
        float q2  = dv * dv;
        float dot = u * cur;
        float mx  = u;
        #pragma unroll
        for (int off = 1; off < 16; off <<= 1) {
            q2  += __shfl_xor_sync(0xffffffffu, q2, off);
            dot += __shfl_xor_sync(0xffffffffu, dot, off);
            mx   = fmaxf(mx, __shfl_xor_sync(0xffffffffu, mx, off));
        }
        if (j == 0 && rok)
            lsum += 0.3f * (q2 * (1.0f / 15.0f)) + 0.5f * dot + 0.2f * mx;
    }
    lsum += __shfl_xor_sync(0xffffffffu, lsum, 16);
    if (lane == 0) s_loss[warp] = lsum;
    __syncthreads();

    // ------------- deterministic single-launch reduction --------------------
    if (tid == 0) {
        float t = 0.0f;
        #pragma unroll
        for (int w = 0; w < 16; ++w) t += s_loss[w];
        g_partials[blockIdx.x] = t;
        __threadfence();
        const unsigned old = atomicAdd(&g_count, 1u);
        *s_last = (old == (unsigned)(nb - 1));
    }
    __syncthreads();

    if (*s_last) {
        float v = 0.0f;
        for (int i = tid; i < nb; i += THR) v += __ldcg(&g_partials[i]);
        s_fin[tid] = v;
        __syncthreads();
        #pragma unroll
        for (int st = 256; st > 0; st >>= 1) {
            if (tid < st) s_fin[tid] += s_fin[tid + st];
            __syncthreads();
        }
        if (tid == 0) {
            out[0] = s_fin[0] * invB;
            g_count = 0;
        }
    }
}

extern "C" void kernel_launch(void* const* d_in, const int* in_sizes, int n_in,
                              void* d_out, int out_size)
{
    const float* pred = (const float*)d_in[0];
    const float* dem  = (const float*)d_in[1];
    const float* clu  = (const float*)d_in[2];
    const float* caps = (const float*)d_in[3];
    const int*   t2l  = (const int*)d_in[4];
    float* out = (float*)d_out;

    const int B  = in_sizes[0] / TUN;           // 16384
    int nb = (B + ROWS - 1) / ROWS;             // 293
    if (nb > 512) nb = 512;

    const int smem_bytes = W_TOTAL * 4;         // ~69.3 KB
    cudaFuncSetAttribute(loss_kernel,
                         cudaFuncAttributeMaxDynamicSharedMemorySize, smem_bytes);
    loss_kernel<<<nb, THR, smem_bytes>>>(pred, dem, clu, caps, t2l, out,
                                         B, nb, 1.0f / (float)B);
}